// round 11
// baseline (speedup 1.0000x reference)
#include <cuda_runtime.h>

#define Bb   8
#define HW   1024
#define Cc   512
#define C4   128
#define NBLK 128
#define NTHR 512
#define DYN_BYTES (64 * 1024)   // weight slab / wbuf

// ---------------- sync counters, one per 128-B line ---------------------------
struct alignas(128) Line { unsigned v; unsigned pad[31]; };
__device__ Line c_cs[8];    // colsum tickets per batch (16 each)
__device__ Line c_xs;       // xsum winners (8)
__device__ Line c_xr[4];    // xr arrivals (64, 16/line)
__device__ Line c_ks[4];    // ksum arrivals (64, 16/line)
__device__ Line c_w;        // w-slice arrivals (16)
__device__ Line c_u;        // u-slice arrivals (16)
__device__ Line c_ep[8];    // epilogue tickets per batch (16 each)
__device__ Line c_fin;      // 8 winners; 8th resets all
__device__ unsigned g_mnk[Bb] = {0xFFFFFFFFu,0xFFFFFFFFu,0xFFFFFFFFu,0xFFFFFFFFu,
                                 0xFFFFFFFFu,0xFFFFFFFFu,0xFFFFFFFFu,0xFFFFFFFFu};
__device__ unsigned g_mxk[Bb] = {0,0,0,0,0,0,0,0};

// ---------------- data scratch (fully rewritten every launch) -----------------
__device__ __align__(16) float4 g_partial4[Bb][16][C4];
__device__ __align__(16) float  g_xsum[Bb][Cc];
__device__ __align__(16) float  g_xr[Bb][Cc];
__device__ __align__(16) float  g_ksum[Bb][Cc];
__device__ __align__(16) float  g_w[Bb][Cc];
__device__ __align__(16) float  g_u[Bb][Cc];
__device__ float g_dot[Bb][HW];

__device__ __forceinline__ unsigned enc(float f) {
    unsigned u = __float_as_uint(f);
    return (u & 0x80000000u) ? ~u : (u | 0x80000000u);
}
__device__ __forceinline__ float dec(unsigned k) {
    return (k & 0x80000000u) ? __uint_as_float(k ^ 0x80000000u)
                             : __uint_as_float(~k);
}

#define ARRIVE(lineptr)                                               \
    do { __syncthreads();                                             \
         if (t == 0) { __threadfence(); atomicAdd(&(lineptr)->v, 1u); } \
    } while (0)
#define WAITGE(arr, n, tgt)                                           \
    do { if (t == 0) {                                                \
             unsigned s_;                                             \
             do { s_ = 0;                                             \
                  _Pragma("unroll")                                   \
                  for (int i_ = 0; i_ < (n); ++i_)                    \
                      s_ += *(volatile const unsigned*)&(arr)[i_].v;  \
             } while (s_ < (unsigned)(tgt));                          \
             __threadfence();                                         \
         }                                                            \
         __syncthreads();                                             \
    } while (0)

__global__ void __launch_bounds__(NTHR)
fused_kernel(const float* __restrict__ x,
             const float* __restrict__ conv_w, const float* __restrict__ conv_b,
             const float* __restrict__ q_w,
             const float* __restrict__ k_w,    const float* __restrict__ k_b,
             float* __restrict__ out)
{
    extern __shared__ float dynsh[];
    float*  wbuf  = dynsh;                     // W blocks: 2 x 8 weight rows
    float4* wbuf4 = reinterpret_cast<float4*>(dynsh);
    float (*slab)[32] = reinterpret_cast<float(*)[32]>(dynsh);  // C/D: [512][32]
    __shared__ __align__(16) float shA[Bb][Cc];             // 16 KB
    __shared__ __align__(16) float shB[Cc];                 // 2 KB
    __shared__ __align__(16) float psum[64][C4];            // 32 KB
    __shared__ float s_part[16][Bb];
    __shared__ float red[16][32][Bb];                       // 16 KB (C/D reduce)
    __shared__ float sdot[64];
    __shared__ unsigned sh_tk;
    float4* shA4 = reinterpret_cast<float4*>(shA);

    const int g    = blockIdx.x;
    const int t    = threadIdx.x;
    const int warp = t >> 5, lane = t & 31;
    const int b_own = g >> 4, s_own = g & 15;
    const int c4t = t & 127, rs = t >> 7;

    // ============ P1: x tile -> registers (+colsum) & weight prefetch ========
    float4 xreg[16];
    {
        const float4* base = reinterpret_cast<const float4*>(x)
                           + ((size_t)(b_own * HW + s_own * 64 + rs * 16)) * C4 + c4t;
        float4 acc = make_float4(0.f, 0.f, 0.f, 0.f);
#pragma unroll
        for (int p = 0; p < 16; ++p) {
            xreg[p] = base[(size_t)p * C4];
            acc.x += xreg[p].x; acc.y += xreg[p].y;
            acc.z += xreg[p].z; acc.w += xreg[p].w;
        }
        shA4[rs * C4 + c4t] = acc;

        // weight prefetch (overlaps x loads)
        if (g >= 64) {                      // W blocks: 8 conv rows + 8 k_w rows
            const float4* s1 = reinterpret_cast<const float4*>(conv_w) + (g - 64) * 1024;
            const float4* s2 = reinterpret_cast<const float4*>(k_w)    + (g - 64) * 1024;
#pragma unroll
            for (int i = 0; i < 2; ++i) wbuf4[t + i * NTHR]        = s1[t + i * NTHR];
#pragma unroll
            for (int i = 0; i < 2; ++i) wbuf4[1024 + t + i * NTHR] = s2[t + i * NTHR];
        } else if (g < 16) {                // C: q_w column slab [:, g*32:+32)
            // thread t loads row t's 32-float segment (one 128-B line)
            const float4* src = reinterpret_cast<const float4*>(q_w + (size_t)t * Cc + g * 32);
#pragma unroll
            for (int i = 0; i < 8; ++i)
                reinterpret_cast<float4*>(slab[t])[i] = src[i];
        } else if (g < 32) {                // D: conv_w column slab [:, (g-16)*32:+32)
            const float4* src = reinterpret_cast<const float4*>(conv_w + (size_t)t * Cc + (g - 16) * 32);
#pragma unroll
            for (int i = 0; i < 8; ++i)
                reinterpret_cast<float4*>(slab[t])[i] = src[i];
        }
        __syncthreads();
        if (t < C4) {
            float4 a = shA4[t], p1 = shA4[C4 + t], p2 = shA4[2 * C4 + t], p3 = shA4[3 * C4 + t];
            a.x += p1.x + p2.x + p3.x;  a.y += p1.y + p2.y + p3.y;
            a.z += p1.z + p2.z + p3.z;  a.w += p1.w + p2.w + p3.w;
            g_partial4[b_own][s_own][t] = a;
        }
    }
    // colsum ticket: 16th block of each batch reduces Xsum (fixed order)
    __syncthreads();
    if (t == 0) { __threadfence(); sh_tk = atomicAdd(&c_cs[b_own].v, 1u); }
    __syncthreads();
    if (sh_tk == 15u) {
        __threadfence();
        const float* gp = &g_partial4[0][0][0].x;
        float a = 0.f;
#pragma unroll
        for (int sp = 0; sp < 16; ++sp)
            a += gp[(b_own * 16 + sp) * Cc + t];
        g_xsum[b_own][t] = a;
        __syncthreads();
        if (t == 0) { __threadfence(); atomicAdd(&c_xs.v, 1u); }
    }

    // ============ W blocks (64..127): xr matvec, then Ksum matvec ============
    if (g >= 64) {
        const int a = g - 64;               // rows [a*8, a*8+8)
        WAITGE(&c_xs, 1, 8);
#pragma unroll
        for (int i = 0; i < 2; ++i)
            shA4[t + i * NTHR] = reinterpret_cast<const float4*>(g_xsum)[t + i * NTHR];
        __syncthreads();
        {   // xr = (conv_w+I) Xsum + HW*conv_b; 2 warps/row
            const int rowL = warp >> 1, h = warp & 1;
            float acc[Bb];
#pragma unroll
            for (int b = 0; b < Bb; ++b) acc[b] = 0.f;
#pragma unroll
            for (int k = 0; k < 2; ++k) {
                const int c4 = h * 64 + k * 32 + lane;
                const float4 wv = wbuf4[rowL * C4 + c4];
#pragma unroll
                for (int b = 0; b < Bb; ++b) {
                    const float4 xa = shA4[b * C4 + c4];
                    acc[b] += wv.x * xa.x + wv.y * xa.y + wv.z * xa.z + wv.w * xa.w;
                }
            }
#pragma unroll
            for (int b = 0; b < Bb; ++b)
#pragma unroll
                for (int off = 16; off; off >>= 1)
                    acc[b] += __shfl_xor_sync(0xffffffffu, acc[b], off);
            if (lane == 0)
#pragma unroll
                for (int b = 0; b < Bb; ++b) s_part[warp][b] = acc[b];
        }
        __syncthreads();
        if (t < 64) {
            const int rL = t >> 3, b = t & 7;
            const int o = a * 8 + rL;
            g_xr[b][o] = s_part[rL * 2][b] + s_part[rL * 2 + 1][b]
                       + (float)HW * conv_b[o] + shA[b][o];
        }
        ARRIVE(&c_xr[a & 3]);
        WAITGE(c_xr, 4, 64);

#pragma unroll
        for (int i = 0; i < 2; ++i)
            shA4[t + i * NTHR] = reinterpret_cast<const float4*>(g_xr)[t + i * NTHR];
        __syncthreads();
        {   // Ksum = k_w xr + HW*k_b
            const int rowL = warp >> 1, h = warp & 1;
            float acc[Bb];
#pragma unroll
            for (int b = 0; b < Bb; ++b) acc[b] = 0.f;
#pragma unroll
            for (int k = 0; k < 2; ++k) {
                const int c4 = h * 64 + k * 32 + lane;
                const float4 wv = wbuf4[1024 + rowL * C4 + c4];
#pragma unroll
                for (int b = 0; b < Bb; ++b) {
                    const float4 xa = shA4[b * C4 + c4];
                    acc[b] += wv.x * xa.x + wv.y * xa.y + wv.z * xa.z + wv.w * xa.w;
                }
            }
#pragma unroll
            for (int b = 0; b < Bb; ++b)
#pragma unroll
                for (int off = 16; off; off >>= 1)
                    acc[b] += __shfl_xor_sync(0xffffffffu, acc[b], off);
            if (lane == 0)
#pragma unroll
                for (int b = 0; b < Bb; ++b) s_part[warp][b] = acc[b];
        }
        __syncthreads();
        if (t < 64) {
            const int rL = t >> 3, b = t & 7;
            const int o = a * 8 + rL;
            g_ksum[b][o] = s_part[rL * 2][b] + s_part[rL * 2 + 1][b]
                         + (float)HW * k_b[o];
        }
        ARRIVE(&c_ks[a & 3]);
    }

    // ============ C blocks (0..15): v + FULL w slice [g*32, +32) =============
    if (g < 16) {
        WAITGE(c_ks, 4, 64);
#pragma unroll
        for (int i = 0; i < 2; ++i)
            shA4[t + i * NTHR] = reinterpret_cast<const float4*>(g_ksum)[t + i * NTHR];
        __syncthreads();
        float tot = 0.f;
#pragma unroll
        for (int b = 0; b < Bb; ++b) tot += shA[b][t];
        shB[t] = tot;
        __syncthreads();
#pragma unroll
        for (int b = 0; b < Bb; ++b) shA[b][t] = shB[t] - shA[b][t];   // v in place
        __syncthreads();

        // w[b][g*32+cc] = sum_o q_w[o][g*32+cc] * v[b][o]  (full o-sum, sliced)
        // thread = (og, cc): og = warp (16 groups of 32 o), cc = lane
        {
            float acc[Bb];
#pragma unroll
            for (int b = 0; b < Bb; ++b) acc[b] = 0.f;
#pragma unroll
            for (int oo = 0; oo < 32; ++oo) {
                const int o = warp * 32 + oo;
                const float wv = slab[o][lane];
#pragma unroll
                for (int b = 0; b < Bb; ++b) acc[b] += wv * shA[b][o];
            }
#pragma unroll
            for (int b = 0; b < Bb; ++b) red[warp][lane][b] = acc[b];
        }
        __syncthreads();
        if (t < 256) {                      // (cc, b) -> reduce 16 og groups
            const int cc = t >> 3, b = t & 7;
            float s = 0.f;
#pragma unroll
            for (int og = 0; og < 16; ++og) s += red[og][cc][b];
            g_w[b][g * 32 + cc] = s;
        }
        ARRIVE(&c_w);
    }

    // ============ D blocks (16..31): FULL u slice [(g-16)*32, +32) ===========
    if (g >= 16 && g < 32) {
        const int j = g - 16;
        WAITGE(&c_w, 1, 16);
        // load full w (8 x 512) into shA
#pragma unroll
        for (int i = 0; i < 2; ++i)
            shA4[t + i * NTHR] = reinterpret_cast<const float4*>(g_w)[t + i * NTHR];
        __syncthreads();

        // u[b][j*32+cc] = sum_o conv_w[o][j*32+cc] * w[b][o] + w[b][j*32+cc]
        {
            float acc[Bb];
#pragma unroll
            for (int b = 0; b < Bb; ++b) acc[b] = 0.f;
#pragma unroll
            for (int oo = 0; oo < 32; ++oo) {
                const int o = warp * 32 + oo;
                const float wv = slab[o][lane];
#pragma unroll
                for (int b = 0; b < Bb; ++b) acc[b] += wv * shA[b][o];
            }
#pragma unroll
            for (int b = 0; b < Bb; ++b) red[warp][lane][b] = acc[b];
        }
        __syncthreads();
        if (t < 256) {
            const int cc = t >> 3, b = t & 7;
            float s = shA[b][j * 32 + cc];  // +w residual
#pragma unroll
            for (int og = 0; og < 16; ++og) s += red[og][cc][b];
            g_u[b][j * 32 + cc] = s;
        }
        ARRIVE(&c_u);
    }

    // ============ all blocks: dot + epilogue =================================
    WAITGE(&c_u, 1, 16);
    {
        shB[t] = g_u[b_own][t];             // 2 KB only
        __syncthreads();

        const float4 uv = reinterpret_cast<const float4*>(shB)[c4t];
#pragma unroll
        for (int p = 0; p < 16; ++p) {
            const float4 xv = xreg[p];
            psum[rs * 16 + p][c4t] =
                xv.x * uv.x + xv.y * uv.y + xv.z * uv.z + xv.w * uv.w;
        }
        __syncthreads();
#pragma unroll
        for (int rr = 0; rr < 4; ++rr) {
            const int row = warp * 4 + rr;
            float sm = psum[row][lane] + psum[row][lane + 32]
                     + psum[row][lane + 64] + psum[row][lane + 96];
#pragma unroll
            for (int off = 16; off; off >>= 1)
                sm += __shfl_xor_sync(0xffffffffu, sm, off);
            if (lane == 0) { sdot[row] = sm; g_dot[b_own][s_own * 64 + row] = sm; }
        }
    }
    __syncthreads();
    if (warp == 0) {
        float v0 = sdot[lane], v1 = sdot[lane + 32];
        float mn = fminf(v0, v1), mx = fmaxf(v0, v1);
#pragma unroll
        for (int off = 16; off; off >>= 1) {
            mn = fminf(mn, __shfl_xor_sync(0xffffffffu, mn, off));
            mx = fmaxf(mx, __shfl_xor_sync(0xffffffffu, mx, off));
        }
        if (lane == 0) {
            atomicMin(&g_mnk[b_own], enc(mn));
            atomicMax(&g_mxk[b_own], enc(mx));
        }
    }
    // epilogue ticket: 16th block of each batch writes outputs + resets
    __syncthreads();
    if (t == 0) { __threadfence(); sh_tk = atomicAdd(&c_ep[b_own].v, 1u); }
    __syncthreads();
    if (sh_tk == 15u) {
        __threadfence();
        const float mn = dec(g_mnk[b_own]);
        const float mx = dec(g_mxk[b_own]);
        const float inv = 1.0f / (mx - mn);
#pragma unroll
        for (int i = 0; i < 2; ++i) {
            const int idx = t + i * NTHR;
            const float z = ((g_dot[b_own][idx] - mn) * inv - 0.65f) / 0.15f;
            out[b_own * HW + idx] = 1.0f / (1.0f + __expf(-z));
        }
        __syncthreads();
        if (t == 0) {
            g_mnk[b_own] = 0xFFFFFFFFu;
            g_mxk[b_own] = 0u;
            c_ep[b_own].v = 0u;
            __threadfence();
            unsigned old = atomicAdd(&c_fin.v, 1u);
            if (old == 7u) {
#pragma unroll
                for (int i = 0; i < 8; ++i) c_cs[i].v = 0u;
#pragma unroll
                for (int i = 0; i < 4; ++i) { c_xr[i].v = 0u; c_ks[i].v = 0u; }
                c_xs.v = 0u; c_w.v = 0u; c_u.v = 0u; c_fin.v = 0u;
                __threadfence();
            }
        }
    }
}

// ---------------------------------------------------------------------------
extern "C" void kernel_launch(void* const* d_in, const int* in_sizes, int n_in,
                              void* d_out, int out_size) {
    const float* x      = (const float*)d_in[0];
    const float* conv_w = (const float*)d_in[1];
    const float* conv_b = (const float*)d_in[2];
    const float* q_w    = (const float*)d_in[3];
    // d_in[4] = q_b: per-batch constant, cancels in min/max normalization.
    const float* k_w    = (const float*)d_in[5];
    const float* k_b    = (const float*)d_in[6];
    float* out = (float*)d_out;

    cudaFuncSetAttribute(fused_kernel,
                         cudaFuncAttributeMaxDynamicSharedMemorySize,
                         DYN_BYTES);
    fused_kernel<<<NBLK, NTHR, DYN_BYTES>>>(x, conv_w, conv_b, q_w, k_w, k_b, out);
}